// round 13
// baseline (speedup 1.0000x reference)
#include <cuda_runtime.h>
#include <cuda_bf16.h>
#include <cuda_fp16.h>
#include <cstdint>

// x: [8,32,256,64] f32 | baseK: [8,64,256,256] f32 | W: [64,224] | b: [64] | y: [8,64,256,64]
#define B_   8
#define F_   32
#define C_   256
#define M_   64
#define CO_  64
#define PAIRS 512
#define LDA  264             // A/X/T row stride (halves): 528B, conflict-free ldmatrix
#define LDW  232             // W row stride (halves): 464B, conflict-free ldmatrix

__device__ __half g_xTh[PAIRS * F_ * C_];             // fp16(x) transposed
__device__ __half g_xT_lo[PAIRS * F_ * C_];           // fp16 residual of x

// ---------------- helpers ----------------
__device__ __forceinline__ uint32_t smem_u32(const void* p) {
    uint32_t a;
    asm("{ .reg .u64 t; cvta.to.shared.u64 t, %1; cvt.u32.u64 %0, t; }" : "=r"(a) : "l"(p));
    return a;
}
__device__ __forceinline__ uint32_t pack_h2(float x, float y) {
    uint32_t r;
    asm("cvt.rn.f16x2.f32 %0, %1, %2;" : "=r"(r) : "f"(y), "f"(x));
    return r;
}
__device__ __forceinline__ void split2h(float x, float y, uint32_t& hi, uint32_t& lo) {
    hi = pack_h2(x, y);
    float hx, hy;
    asm("{ .reg .f16 a,b; mov.b32 {a,b}, %2; cvt.f32.f16 %0, a; cvt.f32.f16 %1, b; }"
        : "=f"(hx), "=f"(hy) : "r"(hi));
    lo = pack_h2(x - hx, y - hy);
}
__device__ __forceinline__ void ldm_x4(uint32_t* r, uint32_t addr) {
    asm volatile("ldmatrix.sync.aligned.m8n8.x4.shared.b16 {%0,%1,%2,%3}, [%4];"
                 : "=r"(r[0]), "=r"(r[1]), "=r"(r[2]), "=r"(r[3]) : "r"(addr));
}
__device__ __forceinline__ void ldm_x4t(uint32_t* r, uint32_t addr) {
    asm volatile("ldmatrix.sync.aligned.m8n8.x4.trans.shared.b16 {%0,%1,%2,%3}, [%4];"
                 : "=r"(r[0]), "=r"(r[1]), "=r"(r[2]), "=r"(r[3]) : "r"(addr));
}
__device__ __forceinline__ void mma_f16(float* d, const uint32_t* a, const uint32_t* b) {
    asm volatile("mma.sync.aligned.m16n8k16.row.col.f32.f16.f16.f32 "
                 "{%0,%1,%2,%3}, {%4,%5,%6,%7}, {%8,%9}, {%0,%1,%2,%3};"
                 : "+f"(d[0]), "+f"(d[1]), "+f"(d[2]), "+f"(d[3])
                 : "r"(a[0]), "r"(a[1]), "r"(a[2]), "r"(a[3]), "r"(b[0]), "r"(b[1]));
}

// ---------------- kernel 0: transpose x -> xTh (fp16) + xT_lo (residual) ----------------
__global__ void transpose_kernel(const float* __restrict__ x) {
    __shared__ float tile[32][33];
    int bf = blockIdx.z;
    int bb = bf >> 5, f = bf & 31;
    int n0 = blockIdx.x * 32, m0 = blockIdx.y * 32;
    int tx = threadIdx.x, ty = threadIdx.y;
    const float* src = x + (size_t)bf * (C_ * M_);
#pragma unroll
    for (int r = 0; r < 32; r += 8)
        tile[ty + r][tx] = src[(size_t)(n0 + ty + r) * M_ + m0 + tx];
    __syncthreads();
#pragma unroll
    for (int r = 0; r < 32; r += 8) {
        int m = m0 + ty + r, n = n0 + tx;
        float v = tile[tx][ty + r];
        __half h = __float2half_rn(v);
        __half lo = __float2half_rn(v - __half2float(h));
        size_t idx = ((size_t)(bb * M_ + m) * F_ + f) * C_ + n;
        g_xTh[idx] = h;
        g_xT_lo[idx] = lo;
    }
}

// ---------------- fused kernel: hops + mix, CTA = pair ----------------
// smem (halves):
//   As  [256][LDA] @ 0        (67584 h)  persistent fp16 A (per base)
//   Xs  [32][LDA]  @ 67584    (8448 h)   fp16 x
//   Ts  [32][LDA]  @ 76032    (8448 h)   Xlo, then U, then V
//   Whi [64][LDW]  @ 84480    (14848 h)
//   Wlo [64][LDW]  @ 99328    (14848 h)
// total 114176 h = 228352 B
#define SM_XS 67584
#define SM_TS 76032
#define SM_WHI 84480
#define SM_WLO 99328
#define FUSED_SMEM 228352
__global__ __launch_bounds__(512, 1)
void fused_kernel(const float* __restrict__ b0,
                  const float* __restrict__ b1,
                  const float* __restrict__ b2,
                  const float* __restrict__ W,
                  const float* __restrict__ bias,
                  float* __restrict__ y) {
    extern __shared__ __align__(16) uint16_t sm[];
    uint16_t* As  = sm;
    uint16_t* Xs  = sm + SM_XS;
    uint16_t* Ts  = sm + SM_TS;

    int pair = blockIdx.x;
    int bb = pair >> 6, m = pair & 63;
    int t = threadIdx.x;
    int w = t >> 5;
    int l = t & 31;
    int g = l >> 2;
    int tig = l & 3;
    int lrow = l & 15;
    int lhalf = (l >> 4) & 1;

    // hop mapping: 16 warps -> 2 f-tiles x 8 v-slices(32)
    int hm = (w >> 3) * 16;
    int hv = (w & 7) * 32;
    // mix mapping: 16 warps -> 4 o-tiles(16) x 4 v-slices(64)
    int mo = (w & 3) * 16;
    int mv = (w >> 2) * 64;

    uint32_t xs_b  = smem_u32(Xs);
    uint32_t ts_b  = smem_u32(Ts);
    uint32_t as_b  = smem_u32(As);
    uint32_t whi_b = smem_u32(sm + SM_WHI);
    uint32_t wlo_b = smem_u32(sm + SM_WLO);

    uint32_t hx_off = (uint32_t)((hm + lrow) * LDA + lhalf * 8) * 2;
    uint32_t hb_off = (uint32_t)(lrow * LDA + hv + lhalf * 8) * 2;
    uint32_t wm_off = (uint32_t)((mo + lrow) * LDW + lhalf * 8) * 2;
    uint32_t mh_row = (uint32_t)(lrow * LDA + mv + lhalf * 8) * 2;   // + ftloc*16*LDA*2 + jj*32

    // ---- load W (split hi/lo) ----
    {
        const float2* W2 = (const float2*)W;       // 7168 float2
        uint32_t* WhiU = (uint32_t*)(sm + SM_WHI);
        uint32_t* WloU = (uint32_t*)(sm + SM_WLO);
#pragma unroll
        for (int r = 0; r < 14; ++r) {
            int i = t + 512 * r;
            int o = i / 112, kk = i % 112;
            float2 wv = W2[i];
            uint32_t hi, lo;
            split2h(wv.x, wv.y, hi, lo);
            WhiU[o * (LDW / 2) + kk] = hi;
            WloU[o * (LDW / 2) + kk] = lo;
        }
    }
    // ---- load Xs (fp16 x), Ts = Xlo ----
    {
        const uint4* sh = (const uint4*)(g_xTh + (size_t)pair * (F_ * C_));
        const uint4* sl = (const uint4*)(g_xT_lo + (size_t)pair * (F_ * C_));
#pragma unroll
        for (int r = 0; r < 2; ++r) {
            int i = t + 512 * r;                   // 1024 uint4
            int f = i >> 5, q = i & 31;
            *(uint4*)&Xs[f * LDA + q * 8] = sh[i];
            *(uint4*)&Ts[f * LDA + q * 8] = sl[i];
        }
    }
    __syncthreads();

    float yacc[8][4];
#pragma unroll
    for (int j = 0; j < 8; ++j)
#pragma unroll
        for (int q = 0; q < 4; ++q) yacc[j][q] = 0.f;

    // ---- mix x block: Whi@Xhi + Wlo@Xhi + Whi@Xlo ----
#pragma unroll
    for (int ft = 0; ft < 2; ++ft) {
        uint32_t wh[4], wl[4];
        ldm_x4(wh, whi_b + wm_off + (uint32_t)ft * 32);
        ldm_x4(wl, wlo_b + wm_off + (uint32_t)ft * 32);
        uint32_t rbase = mh_row + (uint32_t)(ft * 16 * LDA) * 2;
#pragma unroll
        for (int jj = 0; jj < 4; ++jj) {
            uint32_t b4[4], bl4[4];
            ldm_x4t(b4, xs_b + rbase + jj * 32);
            ldm_x4t(bl4, ts_b + rbase + jj * 32);
            mma_f16(yacc[2 * jj],     wh, b4);
            mma_f16(yacc[2 * jj],     wl, b4);
            mma_f16(yacc[2 * jj],     wh, bl4);
            mma_f16(yacc[2 * jj + 1], wh, b4 + 2);
            mma_f16(yacc[2 * jj + 1], wl, b4 + 2);
            mma_f16(yacc[2 * jj + 1], wh, bl4 + 2);
        }
    }

    // ---- per base: hop0 (stream A), hop1 + mixU, mixV ----
    for (int base = 0; base < 3; ++base) {
        const float* A = (base == 0 ? b0 : base == 1 ? b1 : b2) + (size_t)pair * (C_ * C_);
        const float4* A4 = (const float4*)A;

        float acc[4][4];
#pragma unroll
        for (int j = 0; j < 4; ++j)
#pragma unroll
            for (int q = 0; q < 4; ++q) acc[j][q] = 0.f;

        // chunk 0 (32 rows): LDG -> convert -> STS
        float4 ldg[4];
#pragma unroll
        for (int r = 0; r < 4; ++r) ldg[r] = A4[t + 512 * r];
        __syncthreads();     // prior readers of As/Ts done (mix-x or prev base)
#pragma unroll
        for (int r = 0; r < 4; ++r) {
            int i = t + 512 * r;
            int nloc = i >> 6, q = i & 63;
            uint32_t p0 = pack_h2(ldg[r].x, ldg[r].y);
            uint32_t p1 = pack_h2(ldg[r].z, ldg[r].w);
            *(uint2*)&As[nloc * LDA + q * 4] = make_uint2(p0, p1);
        }
        __syncthreads();

        for (int c = 0; c < 8; ++c) {
            if (c + 1 < 8) {
#pragma unroll
                for (int r = 0; r < 4; ++r)
                    ldg[r] = A4[(c + 1) * 2048 + t + 512 * r];
            }
#pragma unroll
            for (int ks = 0; ks < 2; ++ks) {
                int k = c * 32 + ks * 16;
                uint32_t xh[4];
                ldm_x4(xh, xs_b + hx_off + (uint32_t)k * 2);
                uint32_t rofs = hb_off + (uint32_t)(k * LDA) * 2;
#pragma unroll
                for (int jj = 0; jj < 2; ++jj) {
                    uint32_t b4[4];
                    ldm_x4t(b4, as_b + rofs + jj * 32);
                    mma_f16(acc[2 * jj],     xh, b4);
                    mma_f16(acc[2 * jj + 1], xh, b4 + 2);
                }
            }
            if (c + 1 < 8) {
                int rb = (c + 1) * 32;
#pragma unroll
                for (int r = 0; r < 4; ++r) {
                    int i = t + 512 * r;
                    int nloc = i >> 6, q = i & 63;
                    uint32_t p0 = pack_h2(ldg[r].x, ldg[r].y);
                    uint32_t p1 = pack_h2(ldg[r].z, ldg[r].w);
                    *(uint2*)&As[(rb + nloc) * LDA + q * 4] = make_uint2(p0, p1);
                }
            }
            __syncthreads();
        }

        // U -> Ts (fp16)
#pragma unroll
        for (int j = 0; j < 4; ++j) {
            int col = hv + 8 * j + 2 * tig;
            int r0 = hm + g, r1 = hm + g + 8;
            *(uint32_t*)&Ts[r0 * LDA + col] = pack_h2(acc[j][0], acc[j][1]);
            *(uint32_t*)&Ts[r1 * LDA + col] = pack_h2(acc[j][2], acc[j][3]);
        }
        __syncthreads();

        // hop1: V = U@A (reads Ts, As)
#pragma unroll
        for (int j = 0; j < 4; ++j)
#pragma unroll
            for (int q = 0; q < 4; ++q) acc[j][q] = 0.f;
#pragma unroll 4
        for (int ks = 0; ks < 16; ++ks) {
            int k = ks * 16;
            uint32_t xh[4];
            ldm_x4(xh, ts_b + hx_off + (uint32_t)k * 2);
            uint32_t rofs = hb_off + (uint32_t)(k * LDA) * 2;
#pragma unroll
            for (int jj = 0; jj < 2; ++jj) {
                uint32_t b4[4];
                ldm_x4t(b4, as_b + rofs + jj * 32);
                mma_f16(acc[2 * jj],     xh, b4);
                mma_f16(acc[2 * jj + 1], xh, b4 + 2);
            }
        }
        // mixU: y += (Whi+Wlo) @ U  (reads Ts)
        {
            int fbase = 32 + base * 64;
#pragma unroll
            for (int ft = 0; ft < 2; ++ft) {
                uint32_t wh[4], wl[4];
                ldm_x4(wh, whi_b + wm_off + (uint32_t)(fbase + ft * 16) * 2);
                ldm_x4(wl, wlo_b + wm_off + (uint32_t)(fbase + ft * 16) * 2);
                uint32_t rbase = mh_row + (uint32_t)(ft * 16 * LDA) * 2;
#pragma unroll
                for (int jj = 0; jj < 4; ++jj) {
                    uint32_t b4[4];
                    ldm_x4t(b4, ts_b + rbase + jj * 32);
                    mma_f16(yacc[2 * jj],     wh, b4);
                    mma_f16(yacc[2 * jj],     wl, b4);
                    mma_f16(yacc[2 * jj + 1], wh, b4 + 2);
                    mma_f16(yacc[2 * jj + 1], wl, b4 + 2);
                }
            }
        }
        __syncthreads();   // all Ts reads (hop1 + mixU) done

        // V -> Ts (fp16)
#pragma unroll
        for (int j = 0; j < 4; ++j) {
            int col = hv + 8 * j + 2 * tig;
            int r0 = hm + g, r1 = hm + g + 8;
            *(uint32_t*)&Ts[r0 * LDA + col] = pack_h2(acc[j][0], acc[j][1]);
            *(uint32_t*)&Ts[r1 * LDA + col] = pack_h2(acc[j][2], acc[j][3]);
        }
        __syncthreads();

        // mixV: y += (Whi+Wlo) @ V
        {
            int fbase = 64 + base * 64;
#pragma unroll
            for (int ft = 0; ft < 2; ++ft) {
                uint32_t wh[4], wl[4];
                ldm_x4(wh, whi_b + wm_off + (uint32_t)(fbase + ft * 16) * 2);
                ldm_x4(wl, wlo_b + wm_off + (uint32_t)(fbase + ft * 16) * 2);
                uint32_t rbase = mh_row + (uint32_t)(ft * 16 * LDA) * 2;
#pragma unroll
                for (int jj = 0; jj < 4; ++jj) {
                    uint32_t b4[4];
                    ldm_x4t(b4, ts_b + rbase + jj * 32);
                    mma_f16(yacc[2 * jj],     wh, b4);
                    mma_f16(yacc[2 * jj],     wl, b4);
                    mma_f16(yacc[2 * jj + 1], wh, b4 + 2);
                    mma_f16(yacc[2 * jj + 1], wl, b4 + 2);
                }
            }
        }
        // next base's first __syncthreads (before STS chunk0) protects Ts/As reuse
    }

    // ---- epilogue: y + bias ----
#pragma unroll
    for (int j = 0; j < 8; ++j) {
        int col = mv + 8 * j + 2 * tig;
        int r0 = mo + g, r1 = mo + g + 8;
        float bv0 = __ldg(&bias[r0]);
        float bv1 = __ldg(&bias[r1]);
        size_t base0 = ((size_t)(bb * CO_ + r0) * C_ + col) * M_ + m;
        size_t base1 = ((size_t)(bb * CO_ + r1) * C_ + col) * M_ + m;
        y[base0]      = yacc[j][0] + bv0;
        y[base0 + M_] = yacc[j][1] + bv0;
        y[base1]      = yacc[j][2] + bv1;
        y[base1 + M_] = yacc[j][3] + bv1;
    }
}

extern "C" void kernel_launch(void* const* d_in, const int* in_sizes, int n_in,
                              void* d_out, int out_size) {
    const float* x    = (const float*)d_in[0];
    const float* b0   = (const float*)d_in[1];
    const float* b1   = (const float*)d_in[2];
    const float* b2   = (const float*)d_in[3];
    const float* W    = (const float*)d_in[4];
    const float* bias = (const float*)d_in[5];
    float* y = (float*)d_out;

    cudaFuncSetAttribute(fused_kernel, cudaFuncAttributeMaxDynamicSharedMemorySize, FUSED_SMEM);

    transpose_kernel<<<dim3(C_ / 32, M_ / 32, B_ * F_), dim3(32, 8)>>>(x);
    fused_kernel<<<PAIRS, 512, FUSED_SMEM>>>(b0, b1, b2, W, bias, y);
}